// round 7
// baseline (speedup 1.0000x reference)
#include <cuda_runtime.h>

#define NODES 100000
#define EDGES 1600000
#define HCAT  64

// ---------------- static scratch (no runtime allocation allowed) ------------
__device__ float g_xlin1[(size_t)NODES * HCAT];
__device__ float g_xres1[(size_t)NODES * HCAT];
__device__ float g_hbuf [(size_t)NODES * HCAT];
__device__ float g_xlin2[(size_t)NODES * HCAT];
__device__ float g_al1[NODES * 4];
__device__ float g_ar1[NODES * 4];
__device__ float g_al2[NODES];
__device__ float g_ar2[NODES];
__device__ int   g_deg [NODES];
__device__ int   g_offs[NODES + 1];
__device__ int   g_cur [NODES];
__device__ int   g_csr [EDGES];

// ---------------- packed f32x2 helpers ---------------------------------------
typedef unsigned long long ull;

__device__ __forceinline__ ull fma2(ull a, ull b, ull c) {
    ull d;
    asm("fma.rn.f32x2 %0, %1, %2, %3;" : "=l"(d) : "l"(a), "l"(b), "l"(c));
    return d;
}
__device__ __forceinline__ ull pack2(float x) {
    ull r;
    asm("mov.b64 %0, {%1, %1};" : "=l"(r) : "f"(x));
    return r;
}
__device__ __forceinline__ float2 unpack2(ull v) {
    float2 r;
    asm("mov.b64 {%0, %1}, %2;" : "=f"(r.x), "=f"(r.y) : "l"(v));
    return r;
}

// ---------------- CSR build --------------------------------------------------
__global__ void zero_deg_kernel(int* __restrict__ deg) {
    int i = blockIdx.x * blockDim.x + threadIdx.x;
    if (i < NODES) deg[i] = 0;
}

__global__ void hist_kernel(const int* __restrict__ dst, int* __restrict__ deg) {
    int i = blockIdx.x * blockDim.x + threadIdx.x;
    if (i < EDGES) atomicAdd(&deg[dst[i]], 1);
}

__global__ void scan_kernel(const int* __restrict__ deg, int* __restrict__ offs,
                            int* __restrict__ cur) {
    __shared__ int sums[1024];
    int t = threadIdx.x;
    const int CH = (NODES + 1023) / 1024;
    int b = t * CH;
    int e = (b + CH < NODES) ? (b + CH) : NODES;
    int s = 0;
    for (int i = b; i < e; i++) s += deg[i];
    sums[t] = s;
    __syncthreads();
    for (int off = 1; off < 1024; off <<= 1) {
        int v = (t >= off) ? sums[t - off] : 0;
        __syncthreads();
        sums[t] += v;
        __syncthreads();
    }
    int run = sums[t] - s;
    for (int i = b; i < e; i++) {
        offs[i] = run;
        cur[i]  = run;
        run += deg[i];
    }
    if (t == 1023) offs[NODES] = sums[1023];
}

__global__ void scatter_kernel(const int* __restrict__ src, const int* __restrict__ dst,
                               int* __restrict__ cur, int* __restrict__ csr) {
    int i = blockIdx.x * blockDim.x + threadIdx.x;
    if (i < EDGES) {
        int p = atomicAdd(&cur[dst[i]], 1);
        csr[p] = src[i];
    }
}

// ---------------- layer-1 GEMM: X@[W1|Wres], 256x128 tile, 512 thr -----------
// Warp = 8-col group (W loads warp-UNIFORM -> broadcast, ~free on crossbar);
// lane = 8 consecutive rows (2x LDS.128 from transposed x tile).
// 64 B smem per 64 FMA (1.0 B/FMA) vs 1.5 before; FMA becomes the floor.
__global__ void __launch_bounds__(512)
gemm1_kernel(const float* __restrict__ X, const float* __restrict__ W1,
             const float* __restrict__ Wres, const float* __restrict__ attl,
             const float* __restrict__ attr,
             float* __restrict__ xlin, float* __restrict__ xres,
             float* __restrict__ al, float* __restrict__ ar) {
    __shared__ float xs[32 * 260];   // [k][row 0..255], stride 260
    __shared__ float ws[32 * 128];   // [k][col]; reused as alp[] after mainloop
    const int tid  = threadIdx.x;
    const int wid  = tid >> 5;
    const int lane = tid & 31;
    const int row0 = blockIdx.x * 256;
    const int wc   = wid * 8;        // this warp's column base (0..120)

    ull acc[8][4];
#pragma unroll
    for (int r = 0; r < 8; r++)
#pragma unroll
        for (int c = 0; c < 4; c++) acc[r][c] = 0ull;

    const int lr  = tid & 255;        // x-loader row
    const int lkb = (tid >> 8) * 16;  // x-loader k base (0 or 16)

    for (int k0 = 0; k0 < 128; k0 += 32) {
        {   // X tile: 256 rows x 32 k, stored transposed; conflict-free stores
            int gr = row0 + lr;
            const float* xrow = X + (size_t)gr * 128 + k0 + lkb;
#pragma unroll
            for (int j = 0; j < 4; j++) {
                float4 v = make_float4(0.f, 0.f, 0.f, 0.f);
                if (gr < NODES) v = *(const float4*)(xrow + j * 4);
                xs[(lkb + 4 * j + 0) * 260 + lr] = v.x;
                xs[(lkb + 4 * j + 1) * 260 + lr] = v.y;
                xs[(lkb + 4 * j + 2) * 260 + lr] = v.z;
                xs[(lkb + 4 * j + 3) * 260 + lr] = v.w;
            }
        }
        // W tile: 32 k x 128 cols (64 W1 | 64 Wres)
#pragma unroll
        for (int i = 0; i < 2; i++) {
            int flat = tid * 4 + i * 2048;
            int k    = flat >> 7;
            int c    = flat & 127;
            float4 wv;
            if (c < 64)
                wv = *(const float4*)(W1 + (size_t)(k0 + k) * 64 + c);
            else
                wv = *(const float4*)(Wres + (size_t)(k0 + k) * 64 + (c - 64));
            *(float4*)(&ws[k * 128 + c]) = wv;
        }
        __syncthreads();
#pragma unroll 4
        for (int k = 0; k < 32; k++) {
            float4 xa = *(const float4*)(&xs[k * 260 + lane * 8]);      // LDS.128
            float4 xb = *(const float4*)(&xs[k * 260 + lane * 8 + 4]);  // LDS.128
            ulonglong2 w01 = *(const ulonglong2*)(&ws[k * 128 + wc]);       // uniform
            ulonglong2 w23 = *(const ulonglong2*)(&ws[k * 128 + wc + 4]);   // uniform
            ull w0 = w01.x, w1 = w01.y, w2 = w23.x, w3 = w23.y;
            float xr[8] = {xa.x, xa.y, xa.z, xa.w, xb.x, xb.y, xb.z, xb.w};
#pragma unroll
            for (int r = 0; r < 8; r++) {
                ull px = pack2(xr[r]);
                acc[r][0] = fma2(px, w0, acc[r][0]);
                acc[r][1] = fma2(px, w1, acc[r][1]);
                acc[r][2] = fma2(px, w2, acc[r][2]);
                acc[r][3] = fma2(px, w3, acc[r][3]);
            }
        }
        __syncthreads();
    }

    // epilogue: store C; warps 0-7 -> xlin cols wc, warps 8-15 -> xres cols wc-64
    float* alp = ws;                 // reuse: 256 rows * 16 = 4096 floats
    const bool isA = (wid < 8);
    const int  h    = (wc >> 4) & 3; // head for A-warps
    const int  part = wid & 1;       // which half of the head's 16 channels
    float attlv[8], attrv[8];
    if (isA) {
#pragma unroll
        for (int j = 0; j < 8; j++) {
            attlv[j] = attl[wc + j];
            attrv[j] = attr[wc + j];
        }
    }
#pragma unroll
    for (int r = 0; r < 8; r++) {
        int lrow = lane * 8 + r;
        int gr = row0 + lrow;
        float2 f0 = unpack2(acc[r][0]), f1 = unpack2(acc[r][1]);
        float2 f2 = unpack2(acc[r][2]), f3 = unpack2(acc[r][3]);
        float fa[8] = {f0.x, f0.y, f1.x, f1.y, f2.x, f2.y, f3.x, f3.y};
        if (gr < NODES) {
            float* dstp = isA ? (xlin + (size_t)gr * 64 + wc)
                              : (xres + (size_t)gr * 64 + (wc - 64));
            *(float4*)(dstp)     = make_float4(fa[0], fa[1], fa[2], fa[3]);
            *(float4*)(dstp + 4) = make_float4(fa[4], fa[5], fa[6], fa[7]);
        }
        if (isA) {
            float pl = 0.f, pr = 0.f;
#pragma unroll
            for (int j = 0; j < 8; j++) {
                pl += fa[j] * attlv[j];
                pr += fa[j] * attrv[j];
            }
            alp[lrow * 16 + h * 4 + part * 2 + 0] = pl;
            alp[lrow * 16 + h * 4 + part * 2 + 1] = pr;
        }
    }
    __syncthreads();
    // reduce the two halves of each head; 2048 outputs over 512 threads
#pragma unroll
    for (int s = 0; s < 4; s++) {
        int ent = tid + s * 512;            // row*8 + h*2 + sel
        int row = ent >> 3;
        int hh  = (ent >> 1) & 3;
        int sel = ent & 1;
        float v = alp[row * 16 + hh * 4 + 0 + sel] + alp[row * 16 + hh * 4 + 2 + sel];
        int gr = row0 + row;
        if (gr < NODES) {
            if (sel == 0) al[gr * 4 + hh] = v;
            else          ar[gr * 4 + hh] = v;
        }
    }
}

// ---------------- layer-2 GEMM: H@W2, 256x64 tile, 256 thr -------------------
__global__ void __launch_bounds__(256)
gemm2_kernel(const float* __restrict__ X, const float* __restrict__ W,
             const float* __restrict__ attl, const float* __restrict__ attr,
             float* __restrict__ xlin, float* __restrict__ al,
             float* __restrict__ ar) {
    __shared__ float xs[32 * 260];   // reused as alp[] after mainloop
    __shared__ float ws[32 * 64];
    const int tid  = threadIdx.x;
    const int wid  = tid >> 5;       // 0..7, col group
    const int lane = tid & 31;
    const int row0 = blockIdx.x * 256;
    const int wc   = wid * 8;

    ull acc[8][4];
#pragma unroll
    for (int r = 0; r < 8; r++)
#pragma unroll
        for (int c = 0; c < 4; c++) acc[r][c] = 0ull;

    for (int k0 = 0; k0 < 64; k0 += 32) {
        {   // X tile: 256 rows x 32 k; each thread loads its whole row chunk
            int gr = row0 + tid;
            const float* xrow = X + (size_t)gr * 64 + k0;
#pragma unroll
            for (int j = 0; j < 8; j++) {
                float4 v = make_float4(0.f, 0.f, 0.f, 0.f);
                if (gr < NODES) v = *(const float4*)(xrow + j * 4);
                xs[(4 * j + 0) * 260 + tid] = v.x;
                xs[(4 * j + 1) * 260 + tid] = v.y;
                xs[(4 * j + 2) * 260 + tid] = v.z;
                xs[(4 * j + 3) * 260 + tid] = v.w;
            }
        }
#pragma unroll
        for (int i = 0; i < 2; i++) {
            int flat = tid * 4 + i * 1024;
            int k    = flat >> 6;
            int c    = flat & 63;
            float4 wv = *(const float4*)(W + (size_t)(k0 + k) * 64 + c);
            *(float4*)(&ws[k * 64 + c]) = wv;
        }
        __syncthreads();
#pragma unroll 4
        for (int k = 0; k < 32; k++) {
            float4 xa = *(const float4*)(&xs[k * 260 + lane * 8]);
            float4 xb = *(const float4*)(&xs[k * 260 + lane * 8 + 4]);
            ulonglong2 w01 = *(const ulonglong2*)(&ws[k * 64 + wc]);
            ulonglong2 w23 = *(const ulonglong2*)(&ws[k * 64 + wc + 4]);
            ull w0 = w01.x, w1 = w01.y, w2 = w23.x, w3 = w23.y;
            float xr[8] = {xa.x, xa.y, xa.z, xa.w, xb.x, xb.y, xb.z, xb.w};
#pragma unroll
            for (int r = 0; r < 8; r++) {
                ull px = pack2(xr[r]);
                acc[r][0] = fma2(px, w0, acc[r][0]);
                acc[r][1] = fma2(px, w1, acc[r][1]);
                acc[r][2] = fma2(px, w2, acc[r][2]);
                acc[r][3] = fma2(px, w3, acc[r][3]);
            }
        }
        __syncthreads();
    }

    float* alp = xs;                 // 256 rows * 16 slots (8 warps x 2)
    float attlv[8], attrv[8];
#pragma unroll
    for (int j = 0; j < 8; j++) {
        attlv[j] = attl[wc + j];
        attrv[j] = attr[wc + j];
    }
#pragma unroll
    for (int r = 0; r < 8; r++) {
        int lrow = lane * 8 + r;
        int gr = row0 + lrow;
        float2 f0 = unpack2(acc[r][0]), f1 = unpack2(acc[r][1]);
        float2 f2 = unpack2(acc[r][2]), f3 = unpack2(acc[r][3]);
        float fa[8] = {f0.x, f0.y, f1.x, f1.y, f2.x, f2.y, f3.x, f3.y};
        if (gr < NODES) {
            float* dstp = xlin + (size_t)gr * 64 + wc;
            *(float4*)(dstp)     = make_float4(fa[0], fa[1], fa[2], fa[3]);
            *(float4*)(dstp + 4) = make_float4(fa[4], fa[5], fa[6], fa[7]);
        }
        float pl = 0.f, pr = 0.f;
#pragma unroll
        for (int j = 0; j < 8; j++) {
            pl += fa[j] * attlv[j];
            pr += fa[j] * attrv[j];
        }
        alp[lrow * 16 + wid * 2 + 0] = pl;
        alp[lrow * 16 + wid * 2 + 1] = pr;
    }
    __syncthreads();
#pragma unroll
    for (int s = 0; s < 2; s++) {
        int ent = tid + s * 256;        // row*2 + sel
        int row = ent >> 1;
        int sel = ent & 1;
        float v = 0.f;
#pragma unroll
        for (int p = 0; p < 8; p++) v += alp[row * 16 + p * 2 + sel];
        int gr = row0 + row;
        if (gr < NODES) {
            if (sel == 0) al[gr] = v;
            else          ar[gr] = v;
        }
    }
}

// ---------------- fused softmax-attention aggregation (no max pass) ----------
template <int H, int C, bool ELU>
__global__ void __launch_bounds__(256)
agg_kernel(const int* __restrict__ offs, const int* __restrict__ csr,
           const float* __restrict__ xlin, const float* __restrict__ al,
           const float* __restrict__ ar, const float* __restrict__ xres,
           const float* __restrict__ bias, float* __restrict__ out) {
    int w = (blockIdx.x * blockDim.x + threadIdx.x) >> 5;
    if (w >= NODES) return;
    const int lane = threadIdx.x & 31;
    const int hl   = lane & 15;
    const int half = lane >> 4;
    const int myh  = (4 * hl) / C;
    const int o0 = offs[w];
    const int o1 = offs[w + 1];

    const float ar_my = ar[w * H + myh];
    const float4* __restrict__ xl4 = (const float4*)xlin + hl;
    const float*  __restrict__ alh = al + myh;

    float4 acc = make_float4(0.f, 0.f, 0.f, 0.f);
    float  ssum = 0.f;
    for (int i = o0 + half; i < o1; i += 2) {
        int s = csr[i];
        float v = alh[s * H] + ar_my;
        v = v > 0.f ? v : 0.2f * v;
        float e = __expf(v);
        ssum += e;
        float4 xv = xl4[s * 16];
        acc.x += e * xv.x; acc.y += e * xv.y; acc.z += e * xv.z; acc.w += e * xv.w;
    }
    acc.x += __shfl_xor_sync(0xffffffffu, acc.x, 16);
    acc.y += __shfl_xor_sync(0xffffffffu, acc.y, 16);
    acc.z += __shfl_xor_sync(0xffffffffu, acc.z, 16);
    acc.w += __shfl_xor_sync(0xffffffffu, acc.w, 16);
    ssum  += __shfl_xor_sync(0xffffffffu, ssum, 16);

    if (half == 0) {
        float inv = 1.f / (ssum + 1e-16f);
        float4 rv = ((const float4*)xres)[w * 16 + hl];
        float4 bv = ((const float4*)bias)[hl];
        float4 r;
        r.x = acc.x * inv + rv.x + bv.x;
        r.y = acc.y * inv + rv.y + bv.y;
        r.z = acc.z * inv + rv.z + bv.z;
        r.w = acc.w * inv + rv.w + bv.w;
        if (ELU) {
            r.x = r.x > 0.f ? r.x : __expf(r.x) - 1.f;
            r.y = r.y > 0.f ? r.y : __expf(r.y) - 1.f;
            r.z = r.z > 0.f ? r.z : __expf(r.z) - 1.f;
            r.w = r.w > 0.f ? r.w : __expf(r.w) - 1.f;
        }
        ((float4*)out)[w * 16 + hl] = r;
    }
}

// ---------------- launch ------------------------------------------------------
extern "C" void kernel_launch(void* const* d_in, const int* in_sizes, int n_in,
                              void* d_out, int out_size) {
    const float* x     = (const float*)d_in[0];
    const int*   ei    = (const int*)d_in[1];
    const float* W1    = (const float*)d_in[2];
    const float* attl1 = (const float*)d_in[3];
    const float* attr1 = (const float*)d_in[4];
    const float* resW1 = (const float*)d_in[5];
    const float* b1    = (const float*)d_in[6];
    const float* W2    = (const float*)d_in[7];
    const float* attl2 = (const float*)d_in[8];
    const float* attr2 = (const float*)d_in[9];
    const float* b2    = (const float*)d_in[10];
    float* out = (float*)d_out;
    const int* src = ei;
    const int* dst = ei + EDGES;

    float *xlin1, *xres1, *hbuf, *xlin2, *al1, *ar1, *al2, *ar2;
    int *deg, *offs, *cur, *csr;
    cudaGetSymbolAddress((void**)&xlin1, g_xlin1);
    cudaGetSymbolAddress((void**)&xres1, g_xres1);
    cudaGetSymbolAddress((void**)&hbuf,  g_hbuf);
    cudaGetSymbolAddress((void**)&xlin2, g_xlin2);
    cudaGetSymbolAddress((void**)&al1,   g_al1);
    cudaGetSymbolAddress((void**)&ar1,   g_ar1);
    cudaGetSymbolAddress((void**)&al2,   g_al2);
    cudaGetSymbolAddress((void**)&ar2,   g_ar2);
    cudaGetSymbolAddress((void**)&deg,   g_deg);
    cudaGetSymbolAddress((void**)&offs,  g_offs);
    cudaGetSymbolAddress((void**)&cur,   g_cur);
    cudaGetSymbolAddress((void**)&csr,   g_csr);

    const int TB = 256;
    const int GB = (NODES + 255) / 256;          // 391
    const int WG = (NODES * 32 + TB - 1) / TB;   // warp per node

    zero_deg_kernel<<<(NODES + TB - 1) / TB, TB>>>(deg);
    hist_kernel<<<(EDGES + TB - 1) / TB, TB>>>(dst, deg);
    scan_kernel<<<1, 1024>>>(deg, offs, cur);
    gemm1_kernel<<<GB, 512>>>(x, W1, resW1, attl1, attr1, xlin1, xres1, al1, ar1);
    scatter_kernel<<<(EDGES + TB - 1) / TB, TB>>>(src, dst, cur, csr);

    agg_kernel<4, 16, true><<<WG, TB>>>(offs, csr, xlin1, al1, ar1, xres1, b1, hbuf);

    gemm2_kernel<<<GB, 256>>>(hbuf, W2, attl2, attr2, xlin2, al2, ar2);
    agg_kernel<1, 64, false><<<WG, TB>>>(offs, csr, xlin2, al2, ar2, xlin2, b2, out);
}

// round 10
// speedup vs baseline: 1.1214x; 1.1214x over previous
#include <cuda_runtime.h>
#include <cstdint>

#define NODES 100000
#define EDGES 1600000
#define HCAT  64

// ---------------- static scratch (no runtime allocation allowed) ------------
__device__ float g_xlin1[(size_t)NODES * HCAT];
__device__ float g_xres1[(size_t)NODES * HCAT];
__device__ float g_hbuf [(size_t)NODES * HCAT];
__device__ float g_xlin2[(size_t)NODES * HCAT];
__device__ float g_al1[NODES * 4];
__device__ float g_ar1[NODES * 4];
__device__ float g_al2[NODES];
__device__ float g_ar2[NODES];
__device__ int   g_deg [NODES];
__device__ int   g_offs[NODES + 1];
__device__ int   g_cur [NODES];
__device__ int   g_csr [EDGES];

// ---------------- packed f32x2 + async-copy helpers ---------------------------
typedef unsigned long long ull;

__device__ __forceinline__ ull fma2(ull a, ull b, ull c) {
    ull d;
    asm("fma.rn.f32x2 %0, %1, %2, %3;" : "=l"(d) : "l"(a), "l"(b), "l"(c));
    return d;
}
__device__ __forceinline__ ull pack2(float x) {
    ull r;
    asm("mov.b64 %0, {%1, %1};" : "=l"(r) : "f"(x));
    return r;
}
__device__ __forceinline__ float2 unpack2(ull v) {
    float2 r;
    asm("mov.b64 {%0, %1}, %2;" : "=f"(r.x), "=f"(r.y) : "l"(v));
    return r;
}
__device__ __forceinline__ void cp16(unsigned int smem_addr, const void* gptr) {
    asm volatile("cp.async.ca.shared.global [%0], [%1], 16;"
                 :: "r"(smem_addr), "l"(gptr));
}
__device__ __forceinline__ void cp_commit() {
    asm volatile("cp.async.commit_group;");
}
__device__ __forceinline__ void cp_wait0() {
    asm volatile("cp.async.wait_group 0;");
}

// ---------------- CSR build --------------------------------------------------
__global__ void zero_deg_kernel(int* __restrict__ deg) {
    int i = blockIdx.x * blockDim.x + threadIdx.x;
    if (i < NODES) deg[i] = 0;
}

__global__ void hist_kernel(const int* __restrict__ dst, int* __restrict__ deg) {
    int i = blockIdx.x * blockDim.x + threadIdx.x;
    if (i < EDGES) atomicAdd(&deg[dst[i]], 1);
}

__global__ void scan_kernel(const int* __restrict__ deg, int* __restrict__ offs,
                            int* __restrict__ cur) {
    __shared__ int sums[1024];
    int t = threadIdx.x;
    const int CH = (NODES + 1023) / 1024;
    int b = t * CH;
    int e = (b + CH < NODES) ? (b + CH) : NODES;
    int s = 0;
    for (int i = b; i < e; i++) s += deg[i];
    sums[t] = s;
    __syncthreads();
    for (int off = 1; off < 1024; off <<= 1) {
        int v = (t >= off) ? sums[t - off] : 0;
        __syncthreads();
        sums[t] += v;
        __syncthreads();
    }
    int run = sums[t] - s;
    for (int i = b; i < e; i++) {
        offs[i] = run;
        cur[i]  = run;
        run += deg[i];
    }
    if (t == 1023) offs[NODES] = sums[1023];
}

__global__ void scatter_kernel(const int* __restrict__ src, const int* __restrict__ dst,
                               int* __restrict__ cur, int* __restrict__ csr) {
    int i = blockIdx.x * blockDim.x + threadIdx.x;
    if (i < EDGES) {
        int p = atomicAdd(&cur[dst[i]], 1);
        csr[p] = src[i];
    }
}

// ---------------- fused layer-1 GEMM: X@[W1|Wres], double-buffered -----------
// 64 rows x (64+64) cols, BK=32, 256 threads, thread tile 4x(4+4).
// W tiles prefetched via cp.async; X tiles staged through regs, stored after
// compute. One barrier per k0; gmem latency hidden under FFMA2 work.
__global__ void __launch_bounds__(256)
gemm1_kernel(const float* __restrict__ X, const float* __restrict__ W1,
             const float* __restrict__ Wres, const float* __restrict__ attl,
             const float* __restrict__ attr,
             float* __restrict__ xlin, float* __restrict__ xres,
             float* __restrict__ al, float* __restrict__ ar) {
    __shared__ float xs[2][32 * 68];    // [buf][k][row], stride 68
    __shared__ float ws[2][32 * 128];   // [buf][k][col 0:64=W1 | 64:128=Wres]
    const int tid  = threadIdx.x;
    const int cg   = tid & 15;
    const int rg   = tid >> 4;
    const int row0 = blockIdx.x * 64;

    // loader indices (fixed per thread)
    const int lrow0 = (tid * 4) >> 5,          lkk0 = (tid * 4) & 31;
    const int lrow1 = (tid * 4 + 1024) >> 5,   lkk1 = (tid * 4 + 1024) & 31;
    const int gr0 = row0 + lrow0, gr1 = row0 + lrow1;
    const float* xp0 = X + (size_t)gr0 * 128 + lkk0;
    const float* xp1 = X + (size_t)gr1 * 128 + lkk1;

    ull accA[4][2], accB[4][2];
#pragma unroll
    for (int r = 0; r < 4; r++) {
        accA[r][0] = accA[r][1] = 0ull;
        accB[r][0] = accB[r][1] = 0ull;
    }

    // W cp.async issue (4 chunks of 16B per thread)
    auto issueW = [&](int k0, int buf) {
#pragma unroll
        for (int i = 0; i < 4; i++) {
            int flat = tid * 4 + i * 1024;      // 0..4095
            int k    = flat >> 7;
            int c    = flat & 127;
            const float* src = (c < 64)
                ? (W1   + (size_t)(k0 + k) * 64 + c)
                : (Wres + (size_t)(k0 + k) * 64 + (c - 64));
            cp16((unsigned int)__cvta_generic_to_shared(&ws[buf][k * 128 + c]), src);
        }
        cp_commit();
    };
    auto loadX = [&](int k0, float4& v0, float4& v1) {
        v0 = make_float4(0.f, 0.f, 0.f, 0.f);
        v1 = make_float4(0.f, 0.f, 0.f, 0.f);
        if (gr0 < NODES) v0 = *(const float4*)(xp0 + k0);
        if (gr1 < NODES) v1 = *(const float4*)(xp1 + k0);
    };
    auto storeX = [&](int buf, const float4& v0, const float4& v1) {
        xs[buf][(lkk0 + 0) * 68 + lrow0] = v0.x;
        xs[buf][(lkk0 + 1) * 68 + lrow0] = v0.y;
        xs[buf][(lkk0 + 2) * 68 + lrow0] = v0.z;
        xs[buf][(lkk0 + 3) * 68 + lrow0] = v0.w;
        xs[buf][(lkk1 + 0) * 68 + lrow1] = v1.x;
        xs[buf][(lkk1 + 1) * 68 + lrow1] = v1.y;
        xs[buf][(lkk1 + 2) * 68 + lrow1] = v1.z;
        xs[buf][(lkk1 + 3) * 68 + lrow1] = v1.w;
    };

    // prologue: tile 0
    {
        float4 v0, v1;
        loadX(0, v0, v1);
        issueW(0, 0);
        storeX(0, v0, v1);
        cp_wait0();
    }
    __syncthreads();

    int buf = 0;
    for (int k0 = 0; k0 < 128; k0 += 32) {
        const int nk = k0 + 32;
        float4 v0, v1;
        if (nk < 128) {
            loadX(nk, v0, v1);          // LDG in flight during compute
            issueW(nk, buf ^ 1);        // cp.async into other buffer
        }
        const float* xb = xs[buf];
        const float* wb = ws[buf];
#pragma unroll 8
        for (int k = 0; k < 32; k++) {
            float4 xv = *(const float4*)(&xb[k * 68 + rg * 4]);        // LDS.128
            const float* wrow = &wb[k * 128];
            ulonglong2 wA = *(const ulonglong2*)(wrow + cg * 4);       // LDS.128
            ulonglong2 wB = *(const ulonglong2*)(wrow + 64 + cg * 4);  // LDS.128
            ull px0 = pack2(xv.x), px1 = pack2(xv.y);
            ull px2 = pack2(xv.z), px3 = pack2(xv.w);
            accA[0][0] = fma2(px0, wA.x, accA[0][0]);
            accA[0][1] = fma2(px0, wA.y, accA[0][1]);
            accB[0][0] = fma2(px0, wB.x, accB[0][0]);
            accB[0][1] = fma2(px0, wB.y, accB[0][1]);
            accA[1][0] = fma2(px1, wA.x, accA[1][0]);
            accA[1][1] = fma2(px1, wA.y, accA[1][1]);
            accB[1][0] = fma2(px1, wB.x, accB[1][0]);
            accB[1][1] = fma2(px1, wB.y, accB[1][1]);
            accA[2][0] = fma2(px2, wA.x, accA[2][0]);
            accA[2][1] = fma2(px2, wA.y, accA[2][1]);
            accB[2][0] = fma2(px2, wB.x, accB[2][0]);
            accB[2][1] = fma2(px2, wB.y, accB[2][1]);
            accA[3][0] = fma2(px3, wA.x, accA[3][0]);
            accA[3][1] = fma2(px3, wA.y, accA[3][1]);
            accB[3][0] = fma2(px3, wB.x, accB[3][0]);
            accB[3][1] = fma2(px3, wB.y, accB[3][1]);
        }
        if (nk < 128) {
            storeX(buf ^ 1, v0, v1);
            cp_wait0();
            __syncthreads();
            buf ^= 1;
        }
    }

    float4 la = *(const float4*)(attl + cg * 4);
    float4 ra = *(const float4*)(attr + cg * 4);
    const int h = cg >> 2;

#pragma unroll
    for (int r = 0; r < 4; r++) {
        int gr = row0 + rg * 4 + r;
        float2 a0 = unpack2(accA[r][0]), a1 = unpack2(accA[r][1]);
        float2 b0 = unpack2(accB[r][0]), b1 = unpack2(accB[r][1]);
        float4 fa = make_float4(a0.x, a0.y, a1.x, a1.y);
        float4 fb = make_float4(b0.x, b0.y, b1.x, b1.y);
        if (gr < NODES) {
            *(float4*)(xlin + (size_t)gr * 64 + cg * 4) = fa;
            *(float4*)(xres + (size_t)gr * 64 + cg * 4) = fb;
        }
        float pl = fa.x * la.x + fa.y * la.y + fa.z * la.z + fa.w * la.w;
        float pr = fa.x * ra.x + fa.y * ra.y + fa.z * ra.z + fa.w * ra.w;
        pl += __shfl_xor_sync(0xffffffffu, pl, 1);
        pl += __shfl_xor_sync(0xffffffffu, pl, 2);
        pr += __shfl_xor_sync(0xffffffffu, pr, 1);
        pr += __shfl_xor_sync(0xffffffffu, pr, 2);
        if ((cg & 3) == 0 && gr < NODES) {
            al[(size_t)gr * 4 + h] = pl;
            ar[(size_t)gr * 4 + h] = pr;
        }
    }
}

// ---------------- layer-2 GEMM: H@W2 (64x64), double-buffered ----------------
__global__ void __launch_bounds__(256)
gemm2_kernel(const float* __restrict__ X, const float* __restrict__ W,
             const float* __restrict__ attl, const float* __restrict__ attr,
             float* __restrict__ xlin, float* __restrict__ al,
             float* __restrict__ ar) {
    __shared__ float xs[2][32 * 68];
    __shared__ float ws[2][32 * 64];
    const int tid  = threadIdx.x;
    const int cg   = tid & 15;
    const int rg   = tid >> 4;
    const int row0 = blockIdx.x * 64;

    const int lrow0 = (tid * 4) >> 5,          lkk0 = (tid * 4) & 31;
    const int lrow1 = (tid * 4 + 1024) >> 5,   lkk1 = (tid * 4 + 1024) & 31;
    const int gr0 = row0 + lrow0, gr1 = row0 + lrow1;
    const float* xp0 = X + (size_t)gr0 * 64 + lkk0;
    const float* xp1 = X + (size_t)gr1 * 64 + lkk1;

    ull acc[4][2];
#pragma unroll
    for (int r = 0; r < 4; r++) acc[r][0] = acc[r][1] = 0ull;

    auto issueW = [&](int k0, int buf) {
#pragma unroll
        for (int i = 0; i < 2; i++) {
            int flat = tid * 4 + i * 1024;
            int k    = flat >> 6;
            int c    = flat & 63;
            cp16((unsigned int)__cvta_generic_to_shared(&ws[buf][k * 64 + c]),
                 W + (size_t)(k0 + k) * 64 + c);
        }
        cp_commit();
    };
    auto loadX = [&](int k0, float4& v0, float4& v1) {
        v0 = make_float4(0.f, 0.f, 0.f, 0.f);
        v1 = make_float4(0.f, 0.f, 0.f, 0.f);
        if (gr0 < NODES) v0 = *(const float4*)(xp0 + k0);
        if (gr1 < NODES) v1 = *(const float4*)(xp1 + k0);
    };
    auto storeX = [&](int buf, const float4& v0, const float4& v1) {
        xs[buf][(lkk0 + 0) * 68 + lrow0] = v0.x;
        xs[buf][(lkk0 + 1) * 68 + lrow0] = v0.y;
        xs[buf][(lkk0 + 2) * 68 + lrow0] = v0.z;
        xs[buf][(lkk0 + 3) * 68 + lrow0] = v0.w;
        xs[buf][(lkk1 + 0) * 68 + lrow1] = v1.x;
        xs[buf][(lkk1 + 1) * 68 + lrow1] = v1.y;
        xs[buf][(lkk1 + 2) * 68 + lrow1] = v1.z;
        xs[buf][(lkk1 + 3) * 68 + lrow1] = v1.w;
    };

    {
        float4 v0, v1;
        loadX(0, v0, v1);
        issueW(0, 0);
        storeX(0, v0, v1);
        cp_wait0();
    }
    __syncthreads();

    int buf = 0;
    for (int k0 = 0; k0 < 64; k0 += 32) {
        const int nk = k0 + 32;
        float4 v0, v1;
        if (nk < 64) {
            loadX(nk, v0, v1);
            issueW(nk, buf ^ 1);
        }
        const float* xb = xs[buf];
        const float* wb = ws[buf];
#pragma unroll 8
        for (int k = 0; k < 32; k++) {
            float4 xv = *(const float4*)(&xb[k * 68 + rg * 4]);   // LDS.128
            const float* wrow = &wb[k * 64];
            ulonglong2 w01 = *(const ulonglong2*)(wrow + cg * 4); // LDS.128
            ull px0 = pack2(xv.x), px1 = pack2(xv.y);
            ull px2 = pack2(xv.z), px3 = pack2(xv.w);
            acc[0][0] = fma2(px0, w01.x, acc[0][0]);
            acc[0][1] = fma2(px0, w01.y, acc[0][1]);
            acc[1][0] = fma2(px1, w01.x, acc[1][0]);
            acc[1][1] = fma2(px1, w01.y, acc[1][1]);
            acc[2][0] = fma2(px2, w01.x, acc[2][0]);
            acc[2][1] = fma2(px2, w01.y, acc[2][1]);
            acc[3][0] = fma2(px3, w01.x, acc[3][0]);
            acc[3][1] = fma2(px3, w01.y, acc[3][1]);
        }
        if (nk < 64) {
            storeX(buf ^ 1, v0, v1);
            cp_wait0();
            __syncthreads();
            buf ^= 1;
        }
    }

    float4 la = *(const float4*)(attl + cg * 4);
    float4 ra = *(const float4*)(attr + cg * 4);

#pragma unroll
    for (int r = 0; r < 4; r++) {
        int gr = row0 + rg * 4 + r;
        float2 a0 = unpack2(acc[r][0]), a1 = unpack2(acc[r][1]);
        float4 fa = make_float4(a0.x, a0.y, a1.x, a1.y);
        if (gr < NODES)
            *(float4*)(xlin + (size_t)gr * 64 + cg * 4) = fa;
        float pl = fa.x * la.x + fa.y * la.y + fa.z * la.z + fa.w * la.w;
        float pr = fa.x * ra.x + fa.y * ra.y + fa.z * ra.z + fa.w * ra.w;
#pragma unroll
        for (int o = 1; o <= 8; o <<= 1) {
            pl += __shfl_xor_sync(0xffffffffu, pl, o);
            pr += __shfl_xor_sync(0xffffffffu, pr, o);
        }
        if (cg == 0 && gr < NODES) {
            al[gr] = pl;
            ar[gr] = pr;
        }
    }
}

// ---------------- fused softmax-attention aggregation (no max pass) ----------
template <int H, int C, bool ELU>
__global__ void __launch_bounds__(256)
agg_kernel(const int* __restrict__ offs, const int* __restrict__ csr,
           const float* __restrict__ xlin, const float* __restrict__ al,
           const float* __restrict__ ar, const float* __restrict__ xres,
           const float* __restrict__ bias, float* __restrict__ out) {
    int w = (blockIdx.x * blockDim.x + threadIdx.x) >> 5;
    if (w >= NODES) return;
    const int lane = threadIdx.x & 31;
    const int hl   = lane & 15;
    const int half = lane >> 4;
    const int myh  = (4 * hl) / C;
    const int o0 = offs[w];
    const int o1 = offs[w + 1];

    const float ar_my = ar[w * H + myh];
    const float4* __restrict__ xl4 = (const float4*)xlin + hl;
    const float*  __restrict__ alh = al + myh;

    float4 acc = make_float4(0.f, 0.f, 0.f, 0.f);
    float  ssum = 0.f;
    for (int i = o0 + half; i < o1; i += 2) {
        int s = csr[i];
        float v = alh[s * H] + ar_my;
        v = v > 0.f ? v : 0.2f * v;
        float e = __expf(v);
        ssum += e;
        float4 xv = xl4[s * 16];
        acc.x += e * xv.x; acc.y += e * xv.y; acc.z += e * xv.z; acc.w += e * xv.w;
    }
    acc.x += __shfl_xor_sync(0xffffffffu, acc.x, 16);
    acc.y += __shfl_xor_sync(0xffffffffu, acc.y, 16);
    acc.z += __shfl_xor_sync(0xffffffffu, acc.z, 16);
    acc.w += __shfl_xor_sync(0xffffffffu, acc.w, 16);
    ssum  += __shfl_xor_sync(0xffffffffu, ssum, 16);

    if (half == 0) {
        float inv = 1.f / (ssum + 1e-16f);
        float4 rv = ((const float4*)xres)[w * 16 + hl];
        float4 bv = ((const float4*)bias)[hl];
        float4 r;
        r.x = acc.x * inv + rv.x + bv.x;
        r.y = acc.y * inv + rv.y + bv.y;
        r.z = acc.z * inv + rv.z + bv.z;
        r.w = acc.w * inv + rv.w + bv.w;
        if (ELU) {
            r.x = r.x > 0.f ? r.x : __expf(r.x) - 1.f;
            r.y = r.y > 0.f ? r.y : __expf(r.y) - 1.f;
            r.z = r.z > 0.f ? r.z : __expf(r.z) - 1.f;
            r.w = r.w > 0.f ? r.w : __expf(r.w) - 1.f;
        }
        ((float4*)out)[w * 16 + hl] = r;
    }
}

// ---------------- launch ------------------------------------------------------
extern "C" void kernel_launch(void* const* d_in, const int* in_sizes, int n_in,
                              void* d_out, int out_size) {
    const float* x     = (const float*)d_in[0];
    const int*   ei    = (const int*)d_in[1];
    const float* W1    = (const float*)d_in[2];
    const float* attl1 = (const float*)d_in[3];
    const float* attr1 = (const float*)d_in[4];
    const float* resW1 = (const float*)d_in[5];
    const float* b1    = (const float*)d_in[6];
    const float* W2    = (const float*)d_in[7];
    const float* attl2 = (const float*)d_in[8];
    const float* attr2 = (const float*)d_in[9];
    const float* b2    = (const float*)d_in[10];
    float* out = (float*)d_out;
    const int* src = ei;
    const int* dst = ei + EDGES;

    float *xlin1, *xres1, *hbuf, *xlin2, *al1, *ar1, *al2, *ar2;
    int *deg, *offs, *cur, *csr;
    cudaGetSymbolAddress((void**)&xlin1, g_xlin1);
    cudaGetSymbolAddress((void**)&xres1, g_xres1);
    cudaGetSymbolAddress((void**)&hbuf,  g_hbuf);
    cudaGetSymbolAddress((void**)&xlin2, g_xlin2);
    cudaGetSymbolAddress((void**)&al1,   g_al1);
    cudaGetSymbolAddress((void**)&ar1,   g_ar1);
    cudaGetSymbolAddress((void**)&al2,   g_al2);
    cudaGetSymbolAddress((void**)&ar2,   g_ar2);
    cudaGetSymbolAddress((void**)&deg,   g_deg);
    cudaGetSymbolAddress((void**)&offs,  g_offs);
    cudaGetSymbolAddress((void**)&cur,   g_cur);
    cudaGetSymbolAddress((void**)&csr,   g_csr);

    const int TB = 256;
    const int GB = (NODES + 63) / 64;
    const int WG = (NODES * 32 + TB - 1) / TB;   // warp per node

    zero_deg_kernel<<<(NODES + TB - 1) / TB, TB>>>(deg);
    hist_kernel<<<(EDGES + TB - 1) / TB, TB>>>(dst, deg);
    scan_kernel<<<1, 1024>>>(deg, offs, cur);
    gemm1_kernel<<<GB, 256>>>(x, W1, resW1, attl1, attr1, xlin1, xres1, al1, ar1);
    scatter_kernel<<<(EDGES + TB - 1) / TB, TB>>>(src, dst, cur, csr);

    agg_kernel<4, 16, true><<<WG, TB>>>(offs, csr, xlin1, al1, ar1, xres1, b1, hbuf);

    gemm2_kernel<<<GB, 256>>>(hbuf, W2, attl2, attr2, xlin2, al2, ar2);
    agg_kernel<1, 64, false><<<WG, TB>>>(offs, csr, xlin2, al2, ar2, xlin2, b2, out);
}